// round 1
// baseline (speedup 1.0000x reference)
#include <cuda_runtime.h>

// ---------------- problem constants (from reference setup_inputs) ----------
#define BGRAPH 1024
#define FN     32            // nodes (fields) per graph
#define DIN    64
#define HID    128
#define NHEADS 4
#define EPG    256           // template edges per graph (FN * DEG)
#define ETOT   (EPG + FN)    // + self loops = 288
#define H4     (NHEADS * HID) // 512
#define XPAD   132           // padded row stride for [32][128] tiles
#define PPAD   516           // padded row stride for [32][512] tiles
#define NTH    512

// ---------------- shared memory layout (units: floats / ints) --------------
#define SM_XA   0                          // x (gated) / later xp2 : 32*132
#define SM_P    (SM_XA + FN * XPAD)        // aligned -> xp1 -> scratch -> out2 : 32*516
#define SM_HB   (SM_P + FN * PPAD)         // emb staging -> h1 : 32*516
#define SM_LB   (SM_HB + FN * PPAD)        // edge logits/alpha : 288*4
#define SM_AS1  (SM_LB + ETOT * NHEADS)
#define SM_AD1  (SM_AS1 + FN * NHEADS)
#define SM_AS2  (SM_AD1 + FN * NHEADS)
#define SM_AD2  (SM_AS2 + FN)
#define SM_NF   (SM_AD2 + FN)              // total floats = 38720
#define SM_NI   (ETOT * 3 + (FN + 1) + FN) // sl, dl, eidx, off(33), cur(32) = 929
#define SMEM_BYTES ((SM_NF + SM_NI) * 4)

__device__ __forceinline__ void fma4(float4& a, float w, const float4& v) {
    a.x = fmaf(w, v.x, a.x);
    a.y = fmaf(w, v.y, a.y);
    a.z = fmaf(w, v.z, a.z);
    a.w = fmaf(w, v.w, a.w);
}

__global__ __launch_bounds__(NTH, 1)
void gat_fused_kernel(
    const float* __restrict__ emb,    // [B, 32, 64]
    const float* __restrict__ Wal,    // [64, 128]
    const float* __restrict__ bal,    // [128]
    const float* __restrict__ lng,    // [128]
    const float* __restrict__ lnb,    // [128]
    const float* __restrict__ gatel,  // [32]
    const float* __restrict__ W1,     // [128, 512]
    const float* __restrict__ as1w,   // [4, 128]
    const float* __restrict__ ad1w,   // [4, 128]
    const float* __restrict__ b1,     // [512]
    const float* __restrict__ W2,     // [512, 128]
    const float* __restrict__ as2w,   // [128]
    const float* __restrict__ ad2w,   // [128]
    const float* __restrict__ b2,     // [128]
    const int*   __restrict__ esrc,   // [B*256]
    const int*   __restrict__ edst,   // [B*256]
    float*       __restrict__ out,    // [B*128] (+32 gate)
    int write_gate)
{
    extern __shared__ float sm[];
    float* xA   = sm + SM_XA;
    float* P    = sm + SM_P;
    float* Hb   = sm + SM_HB;
    float* lbuf = sm + SM_LB;
    float* as1  = sm + SM_AS1;
    float* ad1  = sm + SM_AD1;
    float* as2  = sm + SM_AS2;
    float* ad2  = sm + SM_AD2;
    int* sSL  = (int*)(sm + SM_NF);
    int* sDL  = sSL + ETOT;
    int* sEI  = sDL + ETOT;
    int* sOFF = sEI + ETOT;   // 33
    int* sCUR = sOFF + (FN + 1); // 32

    const int g    = blockIdx.x;
    const int tid  = threadIdx.x;
    const int lane = tid & 31;
    const int wid  = tid >> 5;

    // ---------- Phase 0: edges, CSR counts, stage emb ----------
    if (tid < FN) sCUR[tid] = 0;
    __syncthreads();
    if (tid < ETOT) {
        int s, d;
        if (tid < EPG) {
            s = esrc[g * EPG + tid] - g * FN;
            d = edst[g * EPG + tid] - g * FN;
        } else {
            s = d = tid - EPG;      // self loops
        }
        sSL[tid] = s;
        sDL[tid] = d;
        atomicAdd(&sCUR[d], 1);
    }
    // stage emb [32][64] -> Hb (2048 floats, one float4 per thread)
    ((float4*)Hb)[tid] = ((const float4*)emb)[(size_t)g * (FN * DIN / 4) + tid];
    __syncthreads();
    if (tid == 0) {
        int r = 0;
        for (int d = 0; d < FN; ++d) {
            sOFF[d] = r;
            r += sCUR[d];
            sCUR[d] = sOFF[d];
        }
        sOFF[FN] = r;
    }
    __syncthreads();
    if (tid < ETOT) {
        int p = atomicAdd(&sCUR[sDL[tid]], 1);
        sEI[p] = tid;
    }

    // ---------- Phase A: align GEMM  aligned = emb @ Wal + bal  -> P[32][128]
    {
        const int m0 = wid * 2;
        float4 a0 = make_float4(0.f, 0.f, 0.f, 0.f);
        float4 a1 = make_float4(0.f, 0.f, 0.f, 0.f);
        const float4* Wv = (const float4*)Wal;   // 32 float4 per row
        #pragma unroll 4
        for (int k = 0; k < DIN; ++k) {
            float x0 = Hb[m0 * DIN + k];
            float x1 = Hb[(m0 + 1) * DIN + k];
            float4 b = Wv[k * 32 + lane];
            fma4(a0, x0, b);
            fma4(a1, x1, b);
        }
        float4 bb = ((const float4*)bal)[lane];
        a0.x += bb.x; a0.y += bb.y; a0.z += bb.z; a0.w += bb.w;
        a1.x += bb.x; a1.y += bb.y; a1.z += bb.z; a1.w += bb.w;
        ((float4*)(P + m0 * HID))[lane]       = a0;
        ((float4*)(P + (m0 + 1) * HID))[lane] = a1;
    }
    __syncthreads();

    // ---------- Phase A2: LayerNorm + sigmoid gate -> xA[32][132] ----------
    {
        #pragma unroll
        for (int rr = 0; rr < 2; ++rr) {
            int r = wid * 2 + rr;
            float v[4];
            float s = 0.f, s2 = 0.f;
            #pragma unroll
            for (int j = 0; j < 4; ++j) {
                v[j] = P[r * HID + j * 32 + lane];
                s  += v[j];
                s2 += v[j] * v[j];
            }
            #pragma unroll
            for (int o = 16; o; o >>= 1) {
                s  += __shfl_xor_sync(0xffffffffu, s, o);
                s2 += __shfl_xor_sync(0xffffffffu, s2, o);
            }
            float mean = s * (1.f / HID);
            float var  = s2 * (1.f / HID) - mean * mean;
            float rstd = rsqrtf(var + 1e-5f);
            float gate = 1.f / (1.f + __expf(-gatel[r]));
            #pragma unroll
            for (int j = 0; j < 4; ++j) {
                int c = j * 32 + lane;
                xA[r * XPAD + c] = ((v[j] - mean) * rstd * lng[c] + lnb[c]) * gate;
            }
        }
    }
    __syncthreads();

    // ---------- Phase B: conv1 GEMM  xp1 = x @ W1  -> P[32][516] -----------
    {
        const int rg = wid >> 2;   // row group: rows rg*8 .. rg*8+7
        const int cg = wid & 3;    // col group: cols cg*128 .. +127
        float4 acc[8];
        #pragma unroll
        for (int i = 0; i < 8; ++i) acc[i] = make_float4(0.f, 0.f, 0.f, 0.f);
        const float4* Wv = (const float4*)W1;    // 128 float4 per row
        #pragma unroll 2
        for (int k = 0; k < HID; ++k) {
            float4 b = Wv[k * 128 + cg * 32 + lane];
            #pragma unroll
            for (int i = 0; i < 8; ++i) {
                float a = xA[(rg * 8 + i) * XPAD + k];
                fma4(acc[i], a, b);
            }
        }
        #pragma unroll
        for (int i = 0; i < 8; ++i)
            ((float4*)(P + (rg * 8 + i) * PPAD + cg * HID))[lane] = acc[i];
    }
    __syncthreads();

    // ---------- Phase C: conv1 attention logits + scatter softmax ----------
    if (tid < FN * NHEADS) {                       // 128 (n,h) pairs
        const int n = tid >> 2, h = tid & 3;
        const float* xr = P + n * PPAD + h * HID;
        const float* aw = as1w + h * HID;
        const float* dw = ad1w + h * HID;
        float ss = 0.f, dd = 0.f;
        #pragma unroll 4
        for (int i = 0; i < HID; ++i) {
            int c = (tid + i) & (HID - 1);         // rotate to spread banks
            float v = xr[c];
            ss = fmaf(v, aw[c], ss);
            dd = fmaf(v, dw[c], dd);
        }
        as1[n * 4 + h] = ss;
        ad1[n * 4 + h] = dd;
    }
    __syncthreads();
    if (tid < ETOT) {
        int s = sSL[tid], d = sDL[tid];
        #pragma unroll
        for (int h = 0; h < NHEADS; ++h) {
            float l = as1[s * 4 + h] + ad1[d * 4 + h];
            lbuf[tid * 4 + h] = (l > 0.f) ? l : 0.2f * l;   // leaky_relu 0.2
        }
    }
    __syncthreads();
    if (tid < FN * NHEADS) {                       // softmax over in-edges of (d,h)
        const int d = tid >> 2, h = tid & 3;
        const int i0 = sOFF[d], i1 = sOFF[d + 1];
        float m = -1e30f;
        for (int i = i0; i < i1; ++i) m = fmaxf(m, lbuf[sEI[i] * 4 + h]);
        float den = 0.f;
        for (int i = i0; i < i1; ++i) {
            float ee = __expf(lbuf[sEI[i] * 4 + h] - m);
            lbuf[sEI[i] * 4 + h] = ee;
            den += ee;
        }
        float inv = 1.f / den;
        for (int i = i0; i < i1; ++i) lbuf[sEI[i] * 4 + h] *= inv;
    }
    __syncthreads();

    // ---------- Phase D: conv1 aggregation + bias1 + ELU -> Hb[32][516] ----
    {
        const int d = tid >> 4, sub = tid & 15;    // 16 threads per dst
        float4 acc[8];
        #pragma unroll
        for (int q = 0; q < 8; ++q) acc[q] = make_float4(0.f, 0.f, 0.f, 0.f);
        const int i0 = sOFF[d], i1 = sOFF[d + 1];
        for (int i = i0; i < i1; ++i) {
            int e = sEI[i];
            int s = sSL[e];
            float w0 = lbuf[e * 4 + 0], w1 = lbuf[e * 4 + 1];
            float w2 = lbuf[e * 4 + 2], w3 = lbuf[e * 4 + 3];
            const float* xr = P + s * PPAD;
            #pragma unroll
            for (int q = 0; q < 8; ++q) {
                int hc = sub * 4 + 64 * q;         // head h = q>>1
                float4 v = *(const float4*)(xr + hc);
                float w = (q < 2) ? w0 : (q < 4) ? w1 : (q < 6) ? w2 : w3;
                fma4(acc[q], w, v);
            }
        }
        #pragma unroll
        for (int q = 0; q < 8; ++q) {
            int hc = sub * 4 + 64 * q;
            float4 bb = *(const float4*)(b1 + hc);
            float4 hv;
            hv.x = acc[q].x + bb.x;
            hv.y = acc[q].y + bb.y;
            hv.z = acc[q].z + bb.z;
            hv.w = acc[q].w + bb.w;
            hv.x = (hv.x > 0.f) ? hv.x : expm1f(hv.x);   // ELU
            hv.y = (hv.y > 0.f) ? hv.y : expm1f(hv.y);
            hv.z = (hv.z > 0.f) ? hv.z : expm1f(hv.z);
            hv.w = (hv.w > 0.f) ? hv.w : expm1f(hv.w);
            *(float4*)(Hb + d * PPAD + hc) = hv;
        }
    }
    __syncthreads();

    // ---------- Phase E: conv2 GEMM  xp2 = h1 @ W2  (k-split 2) -> xA ------
    {
        const int rg = wid & 7;    // rows rg*4 .. +3
        const int ks = wid >> 3;   // k half
        float4 acc[4];
        #pragma unroll
        for (int i = 0; i < 4; ++i) acc[i] = make_float4(0.f, 0.f, 0.f, 0.f);
        const float4* Wv = (const float4*)W2;    // 32 float4 per row
        const int k0 = ks * (H4 / 2);
        #pragma unroll 4
        for (int k = k0; k < k0 + H4 / 2; ++k) {
            float4 b = Wv[k * 32 + lane];
            #pragma unroll
            for (int i = 0; i < 4; ++i) {
                float a = Hb[(rg * 4 + i) * PPAD + k];
                fma4(acc[i], a, b);
            }
        }
        if (ks == 1) {             // stash partials in P scratch [32][128]
            #pragma unroll
            for (int i = 0; i < 4; ++i)
                ((float4*)(P + (rg * 4 + i) * HID))[lane] = acc[i];
        }
        __syncthreads();
        if (ks == 0) {
            #pragma unroll
            for (int i = 0; i < 4; ++i) {
                float4 p = ((float4*)(P + (rg * 4 + i) * HID))[lane];
                acc[i].x += p.x; acc[i].y += p.y; acc[i].z += p.z; acc[i].w += p.w;
                ((float4*)(xA + (rg * 4 + i) * XPAD))[lane] = acc[i];
            }
        }
    }
    __syncthreads();

    // ---------- Phase F: conv2 attention (1 head) --------------------------
    if (tid < FN) {
        const float* xr = xA + tid * XPAD;
        float ss = 0.f, dd = 0.f;
        #pragma unroll 4
        for (int i = 0; i < HID; ++i) {
            int c = (i + tid * 29) & (HID - 1);    // conflict-free rotation
            float v = xr[c];
            ss = fmaf(v, as2w[c], ss);
            dd = fmaf(v, ad2w[c], dd);
        }
        as2[tid] = ss;
        ad2[tid] = dd;
    }
    __syncthreads();
    if (tid < ETOT) {
        float l = as2[sSL[tid]] + ad2[sDL[tid]];
        lbuf[tid] = (l > 0.f) ? l : 0.2f * l;
    }
    __syncthreads();
    if (tid < FN) {
        const int i0 = sOFF[tid], i1 = sOFF[tid + 1];
        float m = -1e30f;
        for (int i = i0; i < i1; ++i) m = fmaxf(m, lbuf[sEI[i]]);
        float den = 0.f;
        for (int i = i0; i < i1; ++i) {
            float ee = __expf(lbuf[sEI[i]] - m);
            lbuf[sEI[i]] = ee;
            den += ee;
        }
        float inv = 1.f / den;
        for (int i = i0; i < i1; ++i) lbuf[sEI[i]] *= inv;
    }
    __syncthreads();

    // ---------- Phase G: conv2 aggregation + bias2 -> P[32][132] -----------
    {
        const int d = tid >> 4, sub = tid & 15;
        float4 acc[2];
        acc[0] = make_float4(0.f, 0.f, 0.f, 0.f);
        acc[1] = make_float4(0.f, 0.f, 0.f, 0.f);
        const int i0 = sOFF[d], i1 = sOFF[d + 1];
        for (int i = i0; i < i1; ++i) {
            int e = sEI[i];
            int s = sSL[e];
            float w = lbuf[e];
            const float* xr = xA + s * XPAD;
            fma4(acc[0], w, *(const float4*)(xr + sub * 4));
            fma4(acc[1], w, *(const float4*)(xr + sub * 4 + 64));
        }
        #pragma unroll
        for (int q = 0; q < 2; ++q) {
            int c = sub * 4 + 64 * q;
            float4 bb = *(const float4*)(b2 + c);
            acc[q].x += bb.x; acc[q].y += bb.y; acc[q].z += bb.z; acc[q].w += bb.w;
            *(float4*)(P + d * XPAD + c) = acc[q];
        }
    }
    __syncthreads();

    // ---------- Phase H: mean pool over 32 nodes -> out --------------------
    if (tid < HID) {
        float s = 0.f;
        #pragma unroll
        for (int n = 0; n < FN; ++n) s += P[n * XPAD + tid];
        out[(size_t)g * HID + tid] = s * (1.f / FN);
    }
    if (write_gate && g == 0 && tid < FN) {
        out[(size_t)BGRAPH * HID + tid] = 1.f / (1.f + __expf(-gatel[tid]));
    }
}

extern "C" void kernel_launch(void* const* d_in, const int* in_sizes, int n_in,
                              void* d_out, int out_size)
{
    const float* emb   = (const float*)d_in[0];
    const float* Wal   = (const float*)d_in[1];
    const float* bal   = (const float*)d_in[2];
    const float* lng   = (const float*)d_in[3];
    const float* lnb   = (const float*)d_in[4];
    const float* gatel = (const float*)d_in[5];
    const float* W1    = (const float*)d_in[6];
    const float* as1w  = (const float*)d_in[7];
    const float* ad1w  = (const float*)d_in[8];
    const float* b1    = (const float*)d_in[9];
    const float* W2    = (const float*)d_in[10];
    const float* as2w  = (const float*)d_in[11];
    const float* ad2w  = (const float*)d_in[12];
    const float* b2    = (const float*)d_in[13];
    const int*   ei    = (const int*)d_in[14];

    const int Et = in_sizes[14] / 2;        // total template edges (B*256)
    const int* esrc = ei;
    const int* edst = ei + Et;

    const int write_gate = (out_size >= BGRAPH * HID + FN) ? 1 : 0;

    cudaFuncSetAttribute(gat_fused_kernel,
                         cudaFuncAttributeMaxDynamicSharedMemorySize, SMEM_BYTES);

    gat_fused_kernel<<<BGRAPH, NTH, SMEM_BYTES>>>(
        emb, Wal, bal, lng, lnb, gatel,
        W1, as1w, ad1w, b1, W2, as2w, ad2w, b2,
        esrc, edst, (float*)d_out, write_gate);
}

// round 2
// speedup vs baseline: 1.5358x; 1.5358x over previous
#include <cuda_runtime.h>

// ---------------- problem constants ----------------------------------------
#define BGRAPH 1024
#define FN     32
#define DIN    64
#define HID    128
#define NHEADS 4
#define EPG    256
#define ETOT   (EPG + FN)       // 288
#define H4     (NHEADS * HID)   // 512
#define XPAD   132              // row-major padded stride for [32][128]
#define PPAD   516              // row-major padded stride for [32][512]
#define XTPAD  34               // transposed stride (even -> b64 aligned)
#define NTH    512

// ---------------- shared memory layout (float offsets) ---------------------
// R3 / xT:  [128][34] transposed gated input  -> later xp2 [32][132]
#define SM_XT   0
#define XT_SZ   (HID * XTPAD)               // 4352
// R1: embT (64*34=2176) + aligned (32*128=4096 at +2176)  -> xp1 [32][516]
//     -> conv2 partials (3*32*128=12288)
#define SM_R1   XT_SZ                       // 4352
#define R1_SZ   (FN * PPAD)                 // 16512
// R2: h1_T [512][34] = 17408  -> later out2 [32][132]
#define SM_R2   (SM_R1 + R1_SZ)             // 20864
#define R2_SZ   (H4 * XTPAD)                // 17408
#define SM_LB   (SM_R2 + R2_SZ)             // 38272  lbuf 288*4
#define SM_AS1  (SM_LB + ETOT * NHEADS)     // 39424
#define SM_AD1  (SM_AS1 + 128)
#define SM_DN1  (SM_AD1 + 128)
#define SM_AS2  (SM_DN1 + 128)
#define SM_AD2  (SM_AS2 + 32)
#define SM_DN2  (SM_AD2 + 32)
#define SM_NF   (SM_DN2 + 32)               // 39904 floats
#define SM_NI   (ETOT * 3 + (FN + 1) + FN)  // 929 ints
#define SMEM_BYTES ((SM_NF + SM_NI) * 4)

typedef unsigned long long ull;

__device__ __forceinline__ ull pk2(float x, float y) {
    ull r; asm("mov.b64 %0, {%1,%2};" : "=l"(r) : "f"(x), "f"(y)); return r;
}
__device__ __forceinline__ ull splat2(float x) { return pk2(x, x); }
__device__ __forceinline__ void upk2(ull p, float& x, float& y) {
    asm("mov.b64 {%0,%1}, %2;" : "=f"(x), "=f"(y) : "l"(p));
}
__device__ __forceinline__ void fma2(ull& d, ull a, ull b) {
    asm("fma.rn.f32x2 %0, %1, %2, %0;" : "+l"(d) : "l"(a), "l"(b));
}
__device__ __forceinline__ void fma4(float4& a, float w, const float4& v) {
    a.x = fmaf(w, v.x, a.x);
    a.y = fmaf(w, v.y, a.y);
    a.z = fmaf(w, v.z, a.z);
    a.w = fmaf(w, v.w, a.w);
}
__device__ __forceinline__ float dot4(const float4& a, const float4& b) {
    return fmaf(a.x, b.x, fmaf(a.y, b.y, fmaf(a.z, b.z, a.w * b.w)));
}
__device__ __forceinline__ float wredsum(float v) {
    #pragma unroll
    for (int o = 16; o; o >>= 1) v += __shfl_xor_sync(0xffffffffu, v, o);
    return v;
}

__global__ __launch_bounds__(NTH, 1)
void gat_fused_kernel(
    const float* __restrict__ emb,    const float* __restrict__ Wal,
    const float* __restrict__ bal,    const float* __restrict__ lng,
    const float* __restrict__ lnb,    const float* __restrict__ gatel,
    const float* __restrict__ W1,     const float* __restrict__ as1w,
    const float* __restrict__ ad1w,   const float* __restrict__ b1,
    const float* __restrict__ W2,     const float* __restrict__ as2w,
    const float* __restrict__ ad2w,   const float* __restrict__ b2,
    const int*   __restrict__ esrc,   const int*   __restrict__ edst,
    float*       __restrict__ out,    int write_gate)
{
    extern __shared__ float sm[];
    float* xT   = sm + SM_XT;             // [128][34]
    float* XP2  = sm + SM_XT;             // later: xp2 [32][132]
    float* embT = sm + SM_R1;             // [64][34]
    float* AL   = sm + SM_R1 + 64 * XTPAD;// aligned [32][128]
    float* XP1  = sm + SM_R1;             // xp1 [32][516]
    float* PART = sm + SM_R1;             // conv2 partials 3*[32][128]
    float* H1T  = sm + SM_R2;             // [512][34]
    float* OUT2 = sm + SM_R2;             // later: [32][132]
    float* lbuf = sm + SM_LB;
    float* as1  = sm + SM_AS1;
    float* ad1  = sm + SM_AD1;
    float* dn1  = sm + SM_DN1;
    float* as2  = sm + SM_AS2;
    float* ad2  = sm + SM_AD2;
    float* dn2  = sm + SM_DN2;
    int* sSL  = (int*)(sm + SM_NF);
    int* sDL  = sSL + ETOT;
    int* sEI  = sDL + ETOT;
    int* sOFF = sEI + ETOT;      // 33
    int* sCUR = sOFF + (FN + 1); // 32

    const int g    = blockIdx.x;
    const int tid  = threadIdx.x;
    const int lane = tid & 31;
    const int wid  = tid >> 5;

    // ---------- Phase 0: stage emb transposed, zero den/counters -----------
    {
        float4 v = ((const float4*)emb)[(size_t)g * (FN * DIN / 4) + tid];
        int r  = tid >> 4;          // node row 0..31
        int c4 = tid & 15;          // feature group
        embT[(c4 * 4 + 0) * XTPAD + r] = v.x;
        embT[(c4 * 4 + 1) * XTPAD + r] = v.y;
        embT[(c4 * 4 + 2) * XTPAD + r] = v.z;
        embT[(c4 * 4 + 3) * XTPAD + r] = v.w;
    }
    if (tid < 128) dn1[tid] = 0.f;
    if (tid < 32)  { dn2[tid] = 0.f; sCUR[tid] = 0; }
    __syncthreads();

    // ---------- Phase A: warps 0-7 align GEMM | warps 8-15 edges/CSR -------
    if (wid < 8) {
        ull acc[2][4];
        #pragma unroll
        for (int p = 0; p < 2; ++p)
            #pragma unroll
            for (int j = 0; j < 4; ++j) acc[p][j] = 0ULL;
        const float4* Wv = (const float4*)Wal;
        #pragma unroll 4
        for (int k = 0; k < DIN; ++k) {
            float4 b = Wv[k * 32 + lane];
            ull b0 = splat2(b.x), b1v = splat2(b.y), b2v = splat2(b.z), b3 = splat2(b.w);
            const ull* ap = (const ull*)(embT + k * XTPAD + wid * 4);
            ull a0 = ap[0], a1 = ap[1];
            fma2(acc[0][0], a0, b0); fma2(acc[0][1], a0, b1v);
            fma2(acc[0][2], a0, b2v); fma2(acc[0][3], a0, b3);
            fma2(acc[1][0], a1, b0); fma2(acc[1][1], a1, b1v);
            fma2(acc[1][2], a1, b2v); fma2(acc[1][3], a1, b3);
        }
        float4 bb = ((const float4*)bal)[lane];
        #pragma unroll
        for (int p = 0; p < 2; ++p) {
            float4 r0, r1;
            upk2(acc[p][0], r0.x, r1.x); upk2(acc[p][1], r0.y, r1.y);
            upk2(acc[p][2], r0.z, r1.z); upk2(acc[p][3], r0.w, r1.w);
            r0.x += bb.x; r0.y += bb.y; r0.z += bb.z; r0.w += bb.w;
            r1.x += bb.x; r1.y += bb.y; r1.z += bb.z; r1.w += bb.w;
            int row = wid * 4 + p * 2;
            ((float4*)(AL + row * HID))[lane]       = r0;
            ((float4*)(AL + (row + 1) * HID))[lane] = r1;
        }
    } else {
        int t = tid - 256;                  // 0..255
        int s = esrc[g * EPG + t] - g * FN;
        int d = edst[g * EPG + t] - g * FN;
        sSL[t] = s; sDL[t] = d;
        atomicAdd(&sCUR[d], 1);
        if (t < FN) { sSL[EPG + t] = t; sDL[EPG + t] = t; atomicAdd(&sCUR[t], 1); }
        asm volatile("bar.sync 1, 256;" ::: "memory");
        if (wid == 8) {
            int c = sCUR[lane];
            int x = c;
            #pragma unroll
            for (int o = 1; o < 32; o <<= 1) {
                int y = __shfl_up_sync(0xffffffffu, x, o);
                if (lane >= o) x += y;
            }
            sOFF[lane + 1] = x;
            if (lane == 0) sOFF[0] = 0;
            sCUR[lane] = x - c;             // exclusive prefix -> cursor
        }
        asm volatile("bar.sync 1, 256;" ::: "memory");
        int p = atomicAdd(&sCUR[d], 1);
        sEI[p] = t;
        if (t < FN) { int p2 = atomicAdd(&sCUR[t], 1); sEI[p2] = EPG + t; }
    }
    __syncthreads();

    // ---------- Phase A2: LayerNorm + gate -> xT (transposed) --------------
    {
        #pragma unroll
        for (int rr = 0; rr < 2; ++rr) {
            int r = wid * 2 + rr;
            float v[4];
            float s = 0.f, s2 = 0.f;
            #pragma unroll
            for (int j = 0; j < 4; ++j) {
                v[j] = AL[r * HID + j * 32 + lane];
                s  += v[j];
                s2 += v[j] * v[j];
            }
            s  = wredsum(s);
            s2 = wredsum(s2);
            float mean = s * (1.f / HID);
            float var  = s2 * (1.f / HID) - mean * mean;
            float rstd = rsqrtf(var + 1e-5f);
            float gate = 1.f / (1.f + __expf(-gatel[r]));
            #pragma unroll
            for (int j = 0; j < 4; ++j) {
                int c = j * 32 + lane;
                xT[c * XTPAD + r] = ((v[j] - mean) * rstd * lng[c] + lnb[c]) * gate;
            }
        }
    }
    __syncthreads();

    // ---------- Phase B: conv1 GEMM (f32x2) + att-dot epilogue -------------
    {
        const int rg = wid >> 2;            // rows rg*8..+7 (pairs rg*4..+3)
        const int h  = wid & 3;             // head / 128-col group
        ull acc[4][4];
        #pragma unroll
        for (int p = 0; p < 4; ++p)
            #pragma unroll
            for (int j = 0; j < 4; ++j) acc[p][j] = 0ULL;
        const float4* Wv = (const float4*)W1;
        #pragma unroll 4
        for (int k = 0; k < HID; ++k) {
            float4 b = Wv[k * 128 + h * 32 + lane];
            ull b0 = splat2(b.x), b1v = splat2(b.y), b2v = splat2(b.z), b3 = splat2(b.w);
            const ull* ap = (const ull*)(xT + k * XTPAD + rg * 8);
            ull a0 = ap[0], a1 = ap[1], a2 = ap[2], a3 = ap[3];
            fma2(acc[0][0], a0, b0); fma2(acc[0][1], a0, b1v);
            fma2(acc[0][2], a0, b2v); fma2(acc[0][3], a0, b3);
            fma2(acc[1][0], a1, b0); fma2(acc[1][1], a1, b1v);
            fma2(acc[1][2], a1, b2v); fma2(acc[1][3], a1, b3);
            fma2(acc[2][0], a2, b0); fma2(acc[2][1], a2, b1v);
            fma2(acc[2][2], a2, b2v); fma2(acc[2][3], a2, b3);
            fma2(acc[3][0], a3, b0); fma2(acc[3][1], a3, b1v);
            fma2(acc[3][2], a3, b2v); fma2(acc[3][3], a3, b3);
        }
        float4 aw = ((const float4*)as1w)[h * 32 + lane];
        float4 dw = ((const float4*)ad1w)[h * 32 + lane];
        #pragma unroll
        for (int p = 0; p < 4; ++p) {
            float4 r0, r1;
            upk2(acc[p][0], r0.x, r1.x); upk2(acc[p][1], r0.y, r1.y);
            upk2(acc[p][2], r0.z, r1.z); upk2(acc[p][3], r0.w, r1.w);
            int row = rg * 8 + p * 2;
            ((float4*)(XP1 + row * PPAD + h * HID))[lane]       = r0;
            ((float4*)(XP1 + (row + 1) * PPAD + h * HID))[lane] = r1;
            float ss0 = wredsum(dot4(r0, aw));
            float dd0 = wredsum(dot4(r0, dw));
            float ss1 = wredsum(dot4(r1, aw));
            float dd1 = wredsum(dot4(r1, dw));
            if (lane == 0) {
                as1[row * 4 + h] = ss0;       ad1[row * 4 + h] = dd0;
                as1[(row + 1) * 4 + h] = ss1; ad1[(row + 1) * 4 + h] = dd1;
            }
        }
    }
    __syncthreads();

    // ---------- Edge pass 1: exp(leaky) + denominator ----------------------
    if (tid < ETOT) {
        int s = sSL[tid], d = sDL[tid];
        float4 ee;
        float* ep = &ee.x;
        #pragma unroll
        for (int h = 0; h < NHEADS; ++h) {
            float l = as1[s * 4 + h] + ad1[d * 4 + h];
            l = (l > 0.f) ? l : 0.2f * l;
            float ex = __expf(l);
            ep[h] = ex;
            atomicAdd(&dn1[d * 4 + h], ex);
        }
        *(float4*)(lbuf + tid * 4) = ee;
    }
    __syncthreads();

    // ---------- Phase D: conv1 aggregation + bias + ELU -> h1_T ------------
    {
        const int d = tid >> 4, sub = tid & 15;
        float4 acc[8];
        #pragma unroll
        for (int q = 0; q < 8; ++q) acc[q] = make_float4(0.f, 0.f, 0.f, 0.f);
        const int i0 = sOFF[d], i1 = sOFF[d + 1];
        for (int i = i0; i < i1; ++i) {
            int e = sEI[i];
            int s = sSL[e];
            float4 al = *(const float4*)(lbuf + e * 4);
            const float* xr = XP1 + s * PPAD;
            #pragma unroll
            for (int q = 0; q < 8; ++q) {
                float4 v = *(const float4*)(xr + sub * 4 + 64 * q);
                float w = (q < 2) ? al.x : (q < 4) ? al.y : (q < 6) ? al.z : al.w;
                fma4(acc[q], w, v);
            }
        }
        float inv[4];
        #pragma unroll
        for (int h = 0; h < 4; ++h) inv[h] = 1.0f / dn1[d * 4 + h];
        #pragma unroll
        for (int q = 0; q < 8; ++q) {
            int hc = sub * 4 + 64 * q;
            float4 bb = *(const float4*)(b1 + hc);
            float iw = inv[q >> 1];
            float4 hv;
            hv.x = fmaf(acc[q].x, iw, bb.x);
            hv.y = fmaf(acc[q].y, iw, bb.y);
            hv.z = fmaf(acc[q].z, iw, bb.z);
            hv.w = fmaf(acc[q].w, iw, bb.w);
            hv.x = (hv.x > 0.f) ? hv.x : expm1f(hv.x);
            hv.y = (hv.y > 0.f) ? hv.y : expm1f(hv.y);
            hv.z = (hv.z > 0.f) ? hv.z : expm1f(hv.z);
            hv.w = (hv.w > 0.f) ? hv.w : expm1f(hv.w);
            H1T[(hc + 0) * XTPAD + d] = hv.x;
            H1T[(hc + 1) * XTPAD + d] = hv.y;
            H1T[(hc + 2) * XTPAD + d] = hv.z;
            H1T[(hc + 3) * XTPAD + d] = hv.w;
        }
    }
    __syncthreads();

    // ---------- Phase E: conv2 GEMM (f32x2, k-split 4) + att epilogue ------
    {
        const int rg = wid & 3;             // rows rg*8..+7
        const int ks = wid >> 2;            // k quarter
        ull acc[4][4];
        #pragma unroll
        for (int p = 0; p < 4; ++p)
            #pragma unroll
            for (int j = 0; j < 4; ++j) acc[p][j] = 0ULL;
        const float4* Wv = (const float4*)W2;
        const int k0 = ks * (H4 / 4);
        #pragma unroll 4
        for (int k = k0; k < k0 + H4 / 4; ++k) {
            float4 b = Wv[k * 32 + lane];
            ull b0 = splat2(b.x), b1v = splat2(b.y), b2v = splat2(b.z), b3 = splat2(b.w);
            const ull* ap = (const ull*)(H1T + k * XTPAD + rg * 8);
            ull a0 = ap[0], a1 = ap[1], a2 = ap[2], a3 = ap[3];
            fma2(acc[0][0], a0, b0); fma2(acc[0][1], a0, b1v);
            fma2(acc[0][2], a0, b2v); fma2(acc[0][3], a0, b3);
            fma2(acc[1][0], a1, b0); fma2(acc[1][1], a1, b1v);
            fma2(acc[1][2], a1, b2v); fma2(acc[1][3], a1, b3);
            fma2(acc[2][0], a2, b0); fma2(acc[2][1], a2, b1v);
            fma2(acc[2][2], a2, b2v); fma2(acc[2][3], a2, b3);
            fma2(acc[3][0], a3, b0); fma2(acc[3][1], a3, b1v);
            fma2(acc[3][2], a3, b2v); fma2(acc[3][3], a3, b3);
        }
        if (ks > 0) {
            #pragma unroll
            for (int p = 0; p < 4; ++p) {
                float4 r0, r1;
                upk2(acc[p][0], r0.x, r1.x); upk2(acc[p][1], r0.y, r1.y);
                upk2(acc[p][2], r0.z, r1.z); upk2(acc[p][3], r0.w, r1.w);
                int row = rg * 8 + p * 2;
                ((float4*)(PART + (ks - 1) * 4096 + row * HID))[lane]       = r0;
                ((float4*)(PART + (ks - 1) * 4096 + (row + 1) * HID))[lane] = r1;
            }
        }
        __syncthreads();
        if (ks == 0) {
            float4 aw = ((const float4*)as2w)[lane];
            float4 dw = ((const float4*)ad2w)[lane];
            #pragma unroll
            for (int p = 0; p < 4; ++p) {
                float4 r0, r1;
                upk2(acc[p][0], r0.x, r1.x); upk2(acc[p][1], r0.y, r1.y);
                upk2(acc[p][2], r0.z, r1.z); upk2(acc[p][3], r0.w, r1.w);
                int row = rg * 8 + p * 2;
                #pragma unroll
                for (int q = 0; q < 3; ++q) {
                    float4 t0 = ((float4*)(PART + q * 4096 + row * HID))[lane];
                    float4 t1 = ((float4*)(PART + q * 4096 + (row + 1) * HID))[lane];
                    r0.x += t0.x; r0.y += t0.y; r0.z += t0.z; r0.w += t0.w;
                    r1.x += t1.x; r1.y += t1.y; r1.z += t1.z; r1.w += t1.w;
                }
                ((float4*)(XP2 + row * XPAD))[lane]       = r0;
                ((float4*)(XP2 + (row + 1) * XPAD))[lane] = r1;
                float ss0 = wredsum(dot4(r0, aw));
                float dd0 = wredsum(dot4(r0, dw));
                float ss1 = wredsum(dot4(r1, aw));
                float dd1 = wredsum(dot4(r1, dw));
                if (lane == 0) {
                    as2[row] = ss0;     ad2[row] = dd0;
                    as2[row + 1] = ss1; ad2[row + 1] = dd1;
                }
            }
        }
    }
    __syncthreads();

    // ---------- Edge pass 2 -------------------------------------------------
    if (tid < ETOT) {
        float l = as2[sSL[tid]] + ad2[sDL[tid]];
        l = (l > 0.f) ? l : 0.2f * l;
        float ex = __expf(l);
        lbuf[tid] = ex;
        atomicAdd(&dn2[sDL[tid]], ex);
    }
    __syncthreads();

    // ---------- Phase G: conv2 aggregation + bias2 -> OUT2 -----------------
    {
        const int d = tid >> 4, sub = tid & 15;
        float4 a0 = make_float4(0.f, 0.f, 0.f, 0.f);
        float4 a1 = make_float4(0.f, 0.f, 0.f, 0.f);
        const int i0 = sOFF[d], i1 = sOFF[d + 1];
        for (int i = i0; i < i1; ++i) {
            int e = sEI[i];
            int s = sSL[e];
            float w = lbuf[e];
            const float* xr = XP2 + s * XPAD;
            fma4(a0, w, *(const float4*)(xr + sub * 4));
            fma4(a1, w, *(const float4*)(xr + sub * 4 + 64));
        }
        float iw = 1.0f / dn2[d];
        float4 bb0 = *(const float4*)(b2 + sub * 4);
        float4 bb1 = *(const float4*)(b2 + sub * 4 + 64);
        a0.x = fmaf(a0.x, iw, bb0.x); a0.y = fmaf(a0.y, iw, bb0.y);
        a0.z = fmaf(a0.z, iw, bb0.z); a0.w = fmaf(a0.w, iw, bb0.w);
        a1.x = fmaf(a1.x, iw, bb1.x); a1.y = fmaf(a1.y, iw, bb1.y);
        a1.z = fmaf(a1.z, iw, bb1.z); a1.w = fmaf(a1.w, iw, bb1.w);
        *(float4*)(OUT2 + d * XPAD + sub * 4)      = a0;
        *(float4*)(OUT2 + d * XPAD + sub * 4 + 64) = a1;
    }
    __syncthreads();

    // ---------- Phase H: mean pool -> out -----------------------------------
    if (tid < HID) {
        float s = 0.f;
        #pragma unroll
        for (int n = 0; n < FN; ++n) s += OUT2[n * XPAD + tid];
        out[(size_t)g * HID + tid] = s * (1.f / FN);
    }
    if (write_gate && g == 0 && tid < FN) {
        out[(size_t)BGRAPH * HID + tid] = 1.f / (1.f + __expf(-gatel[tid]));
    }
}

extern "C" void kernel_launch(void* const* d_in, const int* in_sizes, int n_in,
                              void* d_out, int out_size)
{
    const float* emb   = (const float*)d_in[0];
    const float* Wal   = (const float*)d_in[1];
    const float* bal   = (const float*)d_in[2];
    const float* lng   = (const float*)d_in[3];
    const float* lnb   = (const float*)d_in[4];
    const float* gatel = (const float*)d_in[5];
    const float* W1    = (const float*)d_in[6];
    const float* as1w  = (const float*)d_in[7];
    const float* ad1w  = (const float*)d_in[8];
    const float* b1    = (const float*)d_in[9];
    const float* W2    = (const float*)d_in[10];
    const float* as2w  = (const float*)d_in[11];
    const float* ad2w  = (const float*)d_in[12];
    const float* b2    = (const float*)d_in[13];
    const int*   ei    = (const int*)d_in[14];

    const int Et = in_sizes[14] / 2;
    const int* esrc = ei;
    const int* edst = ei + Et;
    const int write_gate = (out_size >= BGRAPH * HID + FN) ? 1 : 0;

    cudaFuncSetAttribute(gat_fused_kernel,
                         cudaFuncAttributeMaxDynamicSharedMemorySize, SMEM_BYTES);

    gat_fused_kernel<<<BGRAPH, NTH, SMEM_BYTES>>>(
        emb, Wal, bal, lng, lnb, gatel,
        W1, as1w, ad1w, b1, W2, as2w, ad2w, b2,
        esrc, edst, (float*)d_out, write_gate);
}